// round 7
// baseline (speedup 1.0000x reference)
#include <cuda_runtime.h>
#include <cstdint>

// ---------------------------------------------------------------------------
// Fully-fused recurrent relational network, v5c.
// CTA = 4 graphs, 128 threads = 4 warps; warp w owns graph w (rows w*8..w*8+7),
// lane owns cols lane*4..lane*4+3; each THREAD owns all 8 rows x its 4 cols.
// smem = h(16K) + S-scratch(16K) + one 3x8KB cp.async W ring = 56KB
//   -> 4 CTAs/SM, 512-CTA grid = single wave on 148 SMs.
// xw (step-invariant x @ node_w1[0:128] + node_b1) lives in 16 registers.
// Ring tail: commit only real groups; wait depth selected per-iteration
// (no empty commit_group trick).
// ---------------------------------------------------------------------------

#define THREADS 128
#define NG      4
#define MROWS   32
#define BS      2048
#define NSTEPS  8
#define H       128
#define KCH     16                      // k-rows per staged chunk
#define NCHK    (H / KCH)               // 8 chunks per GEMM
#define CHF     (KCH * H)               // 2048 floats = 8KB per chunk

union F2 { float2 f; unsigned long long u; };

__device__ __forceinline__ F2 f2fma(F2 a, F2 b, F2 c) {
    F2 d;
    asm("fma.rn.f32x2 %0, %1, %2, %3;" : "=l"(d.u) : "l"(a.u), "l"(b.u), "l"(c.u));
    return d;
}
__device__ __forceinline__ F2 f2bcast(float x) {
    F2 r; unsigned xi = __float_as_uint(x);
    asm("mov.b64 %0, {%1, %1};" : "=l"(r.u) : "r"(xi));
    return r;
}
__device__ __forceinline__ F2 f2mk(float x, float y) { F2 r; r.f.x = x; r.f.y = y; return r; }

__device__ __forceinline__ void cp_commit() { asm volatile("cp.async.commit_group;" ::: "memory"); }
__device__ __forceinline__ void cp_wait1()  { asm volatile("cp.async.wait_group 1;"  ::: "memory"); }
__device__ __forceinline__ void cp_wait0()  { asm volatile("cp.async.wait_group 0;"  ::: "memory"); }

__device__ __forceinline__ float f4c(const float4& v, int k) {
    return k == 0 ? v.x : k == 1 ? v.y : k == 2 ? v.z : v.w;
}

// Stage one 16x128 chunk (8KB): 512 float4, 4 per thread, coalesced.
__device__ __forceinline__ void stage_chunk(float* ws, const float* __restrict__ W,
                                            int chunk, int t) {
    const float4* src = reinterpret_cast<const float4*>(W + chunk * CHF) + t;
    unsigned dst = (unsigned)__cvta_generic_to_shared(ws) + t * 16;
#pragma unroll
    for (int i = 0; i < 4; ++i) {
        asm volatile("cp.async.cg.shared.global [%0], [%1], 16;"
                     :: "r"(dst + i * 2048), "l"(src + i * 128) : "memory");
    }
}

__device__ __forceinline__ void chunk_fma(const float* __restrict__ in,
                                          const float* __restrict__ wb,
                                          F2 (&acc)[8][2], int r0, int c0, int kb) {
#pragma unroll
    for (int kk = 0; kk < KCH; kk += 4) {
        float4 a[8];
#pragma unroll
        for (int r = 0; r < 8; ++r)
            a[r] = *reinterpret_cast<const float4*>(in + (r0 + r) * H + kb + kk);
#pragma unroll
        for (int k = 0; k < 4; ++k) {
            float4 wv = *reinterpret_cast<const float4*>(wb + (kk + k) * H + c0);
            F2 w0 = f2mk(wv.x, wv.y), w1 = f2mk(wv.z, wv.w);
#pragma unroll
            for (int r = 0; r < 8; ++r) {
                F2 b = f2bcast(f4c(a[r], k));
                acc[r][0] = f2fma(b, w0, acc[r][0]);
                acc[r][1] = f2fma(b, w1, acc[r][1]);
            }
        }
    }
}

// acc += in(own rows) @ W, W streamed via 3-buffer cp.async ring (prefetch depth 2).
// Buffer for chunk ch is (ch % 3).  Chunk ch is staged+committed at iteration
// ch-2 (prologue for 0,1).  At iteration ch, groups in flight are those for
// chunks ch..ch+2 minus completed ones; waiting depth 1 guarantees chunk ch's
// group has completed while keeping one prefetch in flight.  For the last two
// iterations no further stages are issued, so we drain fully (depth 0).
__device__ __forceinline__ void gemm_run(const float* __restrict__ in,
                                         const float* __restrict__ W,
                                         F2 (&acc)[8][2], int r0, int c0, int t,
                                         float* ws) {
    __syncthreads();                       // ring reuse vs previous gemm's readers
    stage_chunk(ws, W, 0, t);            cp_commit();
    stage_chunk(ws + CHF, W, 1, t);      cp_commit();
#pragma unroll
    for (int ch = 0; ch < NCHK; ++ch) {
        if (ch + 2 < NCHK) cp_wait1(); else cp_wait0();
        __syncthreads();
        if (ch + 2 < NCHK) {
            stage_chunk(ws + ((ch + 2) % 3) * CHF, W, ch + 2, t);
            cp_commit();
        }
        chunk_fma(in, ws + (ch % 3) * CHF, acc, r0, c0, ch * KCH);
    }
}

__device__ __forceinline__ void acc_zero(F2 (&acc)[8][2]) {
#pragma unroll
    for (int r = 0; r < 8; ++r) { acc[r][0] = f2mk(0.f, 0.f); acc[r][1] = f2mk(0.f, 0.f); }
}
__device__ __forceinline__ void acc_bias(F2 (&acc)[8][2], const float* __restrict__ bias,
                                         int c0, float s) {
    float4 b = *reinterpret_cast<const float4*>(bias + c0);
#pragma unroll
    for (int r = 0; r < 8; ++r) {
        acc[r][0] = f2mk(b.x * s, b.y * s);
        acc[r][1] = f2mk(b.z * s, b.w * s);
    }
}
__device__ __forceinline__ void acc_from_smem(F2 (&acc)[8][2], const float* __restrict__ src,
                                              int r0, int c0) {
#pragma unroll
    for (int r = 0; r < 8; ++r) {
        float4 v = *reinterpret_cast<const float4*>(src + (r0 + r) * H + c0);
        acc[r][0] = f2mk(v.x, v.y);
        acc[r][1] = f2mk(v.z, v.w);
    }
}
__device__ __forceinline__ void acc_store(float* __restrict__ out, F2 (&acc)[8][2],
                                          int r0, int c0, bool relu) {
#pragma unroll
    for (int r = 0; r < 8; ++r) {
        float4 v = make_float4(acc[r][0].f.x, acc[r][0].f.y, acc[r][1].f.x, acc[r][1].f.y);
        if (relu) {
            v.x = fmaxf(v.x, 0.f); v.y = fmaxf(v.y, 0.f);
            v.z = fmaxf(v.z, 0.f); v.w = fmaxf(v.w, 0.f);
        }
        *reinterpret_cast<float4*>(out + (r0 + r) * H + c0) = v;
    }
}

__global__ void __launch_bounds__(THREADS, 4)
rrn_kernel(const int* __restrict__ sources, const int* __restrict__ targets,
           const int* __restrict__ types, const int* __restrict__ diffs,
           const int* __restrict__ question,
           const float* __restrict__ pre_w1, const float* __restrict__ pre_b1,
           const float* __restrict__ pre_w2, const float* __restrict__ pre_b2,
           const float* __restrict__ msg_w1, const float* __restrict__ msg_b1,
           const float* __restrict__ msg_w2, const float* __restrict__ msg_b2,
           const float* __restrict__ node_w1, const float* __restrict__ node_b1,
           const float* __restrict__ node_w2, const float* __restrict__ node_b2,
           const float* __restrict__ out_w1, const float* __restrict__ out_b1,
           const float* __restrict__ out_w2, const float* __restrict__ out_b2,
           float* __restrict__ out)
{
    extern __shared__ float sm[];
    float* sh_h = sm;                     // current hidden state (16KB)
    float* sh_S = sm + 4096;              // scratch: feats / A / S / m_agg / hidden / pooled
    float* ws   = sm + 8192;              // cp.async W ring: 3 x 8KB

    const int t    = threadIdx.x;
    const int cta  = blockIdx.x;
    const int warp = t >> 5;              // == graph within CTA
    const int r0   = warp * 8;
    const int c0   = (t & 31) * 4;

    // ---- pre-MLP hidden = relu(one-hot gather of pre_w1 rows + b1) -> sh_S
    {
        const float b1 = pre_b1[t];
        for (int m = 0; m < MROWS; ++m) {
            const int node = cta * MROWS + m;
            const int b  = node >> 3;
            const int s  = sources[node];
            const int tg = targets[node];
            const int ty = types[node];
            const int d  = diffs[node];
            const int q  = question[b];
            float v = pre_w1[s * H + t] + pre_w1[(8 + tg) * H + t]
                    + pre_w1[(16 + ty) * H + t] + pre_w1[(19 + d) * H + t]
                    + pre_w1[(119 + q) * H + t] + b1;
            sh_S[m * H + t] = fmaxf(v, 0.f);
        }
    }
    __syncthreads();

    // ---- x = hidden @ pre_w2 + pre_b2 -> sh_h  (h0 = x)
    {
        F2 acc[8][2];
        acc_bias(acc, pre_b2, c0, 1.0f);
        gemm_run(sh_S, pre_w2, acc, r0, c0, t, ws);
        acc_store(sh_h, acc, r0, c0, false);
        __syncwarp();
    }

    // ---- xw = x @ node_w1[0:128] + node_b1  (kept in registers, step-invariant)
    F2 xw[8][2];
    acc_bias(xw, node_b1, c0, 1.0f);
    gemm_run(sh_h, node_w1, xw, r0, c0, t, ws);

    const float4 b1v = *reinterpret_cast<const float4*>(msg_b1 + c0);
    const float bias1[4] = {b1v.x, b1v.y, b1v.z, b1v.w};

    for (int step = 0; step < NSTEPS; ++step) {
        // A = h @ msg_w1[0:128]  -> park in sh_S (own slots)
        {
            F2 acc[8][2];
            acc_zero(acc);
            gemm_run(sh_h, msg_w1, acc, r0, c0, t, ws);
            acc_store(sh_S, acc, r0, c0, false);
        }
        // B = h @ msg_w1[128:256]  (registers)
        F2 accB[8][2];
        acc_zero(accB);
        gemm_run(sh_h, msg_w1 + 128 * H, accB, r0, c0, t, ws);

        // S_i = sum_{j != i} relu(A_i + B_j + b1): thread-local (8 rows x 4 cols)
        {
            F2 accA[8][2];
            acc_from_smem(accA, sh_S, r0, c0);   // reload A (same thread wrote it)
#pragma unroll
            for (int cc = 0; cc < 4; ++cc) {
                const int p = cc >> 1, hl = cc & 1;
                float A[8], Bv[8];
#pragma unroll
                for (int r = 0; r < 8; ++r) {
                    A[r]  = hl ? accA[r][p].f.y : accA[r][p].f.x;
                    Bv[r] = hl ? accB[r][p].f.y : accB[r][p].f.x;
                }
                const float bc = bias1[cc];
#pragma unroll
                for (int i = 0; i < 8; ++i) {
                    float s = 0.f;
#pragma unroll
                    for (int j = 0; j < 8; ++j) s += fmaxf(A[i] + Bv[j] + bc, 0.f);
                    s -= fmaxf(A[i] + Bv[i] + bc, 0.f);    // drop self-edge
                    if (hl) accA[i][p].f.y = s; else accA[i][p].f.x = s;
                }
            }
            acc_store(sh_S, accA, r0, c0, false);          // S -> own slots
            __syncwarp();
        }

        // m_agg = S @ msg_w2 + 7*msg_b2 -> sh_S (own slots)
        {
            F2 acc[8][2];
            acc_bias(acc, msg_b2, c0, 7.0f);
            gemm_run(sh_S, msg_w2, acc, r0, c0, t, ws);
            acc_store(sh_S, acc, r0, c0, false);
            __syncwarp();
        }

        // hidden = relu(xw + h@Wn1b + m_agg@Wn1c) -> sh_S (own slots)
        {
            F2 acc[8][2];
#pragma unroll
            for (int r = 0; r < 8; ++r) { acc[r][0] = xw[r][0]; acc[r][1] = xw[r][1]; }
            gemm_run(sh_h, node_w1 + 128 * H, acc, r0, c0, t, ws);
            gemm_run(sh_S, node_w1 + 256 * H, acc, r0, c0, t, ws);
            acc_store(sh_S, acc, r0, c0, true);
            __syncwarp();
        }

        // h_new = hidden @ node_w2 + node_b2 -> sh_h ; pooled from regs
        {
            F2 acc[8][2];
            acc_bias(acc, node_b2, c0, 1.0f);
            gemm_run(sh_S, node_w2, acc, r0, c0, t, ws);
            acc_store(sh_h, acc, r0, c0, false);
            float4 pool = make_float4(0.f, 0.f, 0.f, 0.f);
#pragma unroll
            for (int r = 0; r < 8; ++r) {
                pool.x += acc[r][0].f.x; pool.y += acc[r][0].f.y;
                pool.z += acc[r][1].f.x; pool.w += acc[r][1].f.y;
            }
            __syncthreads();               // all warps done reading sh_S rows
            *reinterpret_cast<float4*>(sh_S + warp * H + c0) = pool;  // row g = graph g
        }
        __syncthreads();

        // out hidden = relu(pooled @ out_w1 + out_b1) -> sh_S rows 4..7
        {
            float acc[NG];
            const float ob = out_b1[t];
#pragma unroll
            for (int g = 0; g < NG; ++g) acc[g] = ob;
#pragma unroll 8
            for (int k = 0; k < H; ++k) {
                const float w = out_w1[k * H + t];
#pragma unroll
                for (int g = 0; g < NG; ++g) acc[g] += sh_S[g * H + k] * w;
            }
#pragma unroll
            for (int g = 0; g < NG; ++g) sh_S[(4 + g) * H + t] = fmaxf(acc[g], 0.f);
        }
        __syncthreads();

        // logits = oh @ out_w2 + out_b2 -> gmem [step][bs][100]
        if (t < 100) {
            float acc[NG];
            const float ob = out_b2[t];
#pragma unroll
            for (int g = 0; g < NG; ++g) acc[g] = ob;
#pragma unroll 8
            for (int k = 0; k < H; ++k) {
                const float w = out_w2[k * 100 + t];
#pragma unroll
                for (int g = 0; g < NG; ++g) acc[g] += sh_S[(4 + g) * H + k] * w;
            }
#pragma unroll
            for (int g = 0; g < NG; ++g)
                out[(step * BS + cta * NG + g) * 100 + t] = acc[g];
        }
        // next iteration's first gemm_run begins with __syncthreads
    }
}

extern "C" void kernel_launch(void* const* d_in, const int* in_sizes, int n_in,
                              void* d_out, int out_size) {
    (void)in_sizes; (void)n_in; (void)out_size;
    const int*   sources  = (const int*)  d_in[0];
    const int*   targets  = (const int*)  d_in[1];
    const int*   types    = (const int*)  d_in[2];
    const int*   diffs    = (const int*)  d_in[3];
    const int*   question = (const int*)  d_in[4];
    const float* pre_w1   = (const float*)d_in[5];
    const float* pre_b1   = (const float*)d_in[6];
    const float* pre_w2   = (const float*)d_in[7];
    const float* pre_b2   = (const float*)d_in[8];
    const float* msg_w1   = (const float*)d_in[9];
    const float* msg_b1   = (const float*)d_in[10];
    const float* msg_w2   = (const float*)d_in[11];
    const float* msg_b2   = (const float*)d_in[12];
    const float* node_w1  = (const float*)d_in[13];
    const float* node_b1  = (const float*)d_in[14];
    const float* node_w2  = (const float*)d_in[15];
    const float* node_b2  = (const float*)d_in[16];
    const float* out_w1   = (const float*)d_in[17];
    const float* out_b1   = (const float*)d_in[18];
    const float* out_w2   = (const float*)d_in[19];
    const float* out_b2   = (const float*)d_in[20];

    const size_t smem = (2 * 4096 + 3 * CHF) * sizeof(float);  // 32KB + 24KB = 56KB
    cudaFuncSetAttribute(rrn_kernel, cudaFuncAttributeMaxDynamicSharedMemorySize,
                         (int)smem);

    rrn_kernel<<<BS / NG, THREADS, smem>>>(
        sources, targets, types, diffs, question,
        pre_w1, pre_b1, pre_w2, pre_b2,
        msg_w1, msg_b1, msg_w2, msg_b2,
        node_w1, node_b1, node_w2, node_b2,
        out_w1, out_b1, out_w2, out_b2,
        (float*)d_out);
}

// round 9
// speedup vs baseline: 1.0067x; 1.0067x over previous
#include <cuda_runtime.h>
#include <cstdint>

// ---------------------------------------------------------------------------
// Fully-fused recurrent relational network, v6.
// CTA = 4 graphs, 128 threads = 4 warps; warp w owns graph w (rows w*8..w*8+7),
// lane owns cols lane*4..lane*4+3; each THREAD owns all 8 rows x its 4 cols.
// smem = h(16K) + S-scratch(16K) + one 3x8KB cp.async W ring = 56KB
//   -> 4 CTAs/SM, 512-CTA grid = single wave.
// xw (step-invariant x @ node_w1[0:128] + node_b1) lives in an 8MB __device__
// scratch (read back 8x per CTA from L2, own-thread coalesced float4s).
// Weight staging is ONE continuous cp.async chain across all GEMMs: each
// GEMM's tail iterations prefetch the next GEMM's first chunks, so the async
// pipe never drains (no per-GEMM prologue bubble).
// ---------------------------------------------------------------------------

#define THREADS 128
#define NG      4
#define MROWS   32
#define BS      2048
#define NSTEPS  8
#define H       128
#define KCH     16                      // k-rows per staged chunk
#define NCHK    (H / KCH)               // 8 chunks per GEMM
#define CHF     (KCH * H)               // 2048 floats = 8KB per chunk

__device__ float g_xw[BS * 8 * H];      // 8MB step-invariant xw scratch

union F2 { float2 f; unsigned long long u; };

__device__ __forceinline__ F2 f2fma(F2 a, F2 b, F2 c) {
    F2 d;
    asm("fma.rn.f32x2 %0, %1, %2, %3;" : "=l"(d.u) : "l"(a.u), "l"(b.u), "l"(c.u));
    return d;
}
__device__ __forceinline__ F2 f2bcast(float x) {
    F2 r; unsigned xi = __float_as_uint(x);
    asm("mov.b64 %0, {%1, %1};" : "=l"(r.u) : "r"(xi));
    return r;
}
__device__ __forceinline__ F2 f2mk(float x, float y) { F2 r; r.f.x = x; r.f.y = y; return r; }

__device__ __forceinline__ void cp_commit() { asm volatile("cp.async.commit_group;" ::: "memory"); }
__device__ __forceinline__ void cp_wait1()  { asm volatile("cp.async.wait_group 1;"  ::: "memory"); }
__device__ __forceinline__ void cp_wait0()  { asm volatile("cp.async.wait_group 0;"  ::: "memory"); }

__device__ __forceinline__ float f4c(const float4& v, int k) {
    return k == 0 ? v.x : k == 1 ? v.y : k == 2 ? v.z : v.w;
}

// Stage one 16x128 chunk (8KB) at src into ws: 512 float4, 4 per thread.
__device__ __forceinline__ void stage_chunk(float* ws, const float* __restrict__ src,
                                            int t) {
    const float4* s = reinterpret_cast<const float4*>(src) + t;
    unsigned dst = (unsigned)__cvta_generic_to_shared(ws) + t * 16;
#pragma unroll
    for (int i = 0; i < 4; ++i) {
        asm volatile("cp.async.cg.shared.global [%0], [%1], 16;"
                     :: "r"(dst + i * 2048), "l"(s + i * 128) : "memory");
    }
}

__device__ __forceinline__ void chunk_fma(const float* __restrict__ in,
                                          const float* __restrict__ wb,
                                          F2 (&acc)[8][2], int r0, int c0, int kb) {
#pragma unroll
    for (int kk = 0; kk < KCH; kk += 4) {
        float4 a[8];
#pragma unroll
        for (int r = 0; r < 8; ++r)
            a[r] = *reinterpret_cast<const float4*>(in + (r0 + r) * H + kb + kk);
#pragma unroll
        for (int k = 0; k < 4; ++k) {
            float4 wv = *reinterpret_cast<const float4*>(wb + (kk + k) * H + c0);
            F2 w0 = f2mk(wv.x, wv.y), w1 = f2mk(wv.z, wv.w);
#pragma unroll
            for (int r = 0; r < 8; ++r) {
                F2 b = f2bcast(f4c(a[r], k));
                acc[r][0] = f2fma(b, w0, acc[r][0]);
                acc[r][1] = f2fma(b, w1, acc[r][1]);
            }
        }
    }
}

// acc += in(own rows) @ W.  Continuous chain: chunk ch's buffer is `slot`
// (carried across calls); each iteration prefetches two chunks ahead — from W
// while inside this GEMM, from Wnext for the last two iterations.  wait1 keeps
// exactly one prefetch in flight while guaranteeing the compute chunk landed.
__device__ __forceinline__ void gemm_chain(const float* __restrict__ in,
                                           const float* __restrict__ W,
                                           const float* __restrict__ Wnext,
                                           F2 (&acc)[8][2], int r0, int c0, int t,
                                           float* ws, int& slot) {
#pragma unroll
    for (int ch = 0; ch < NCHK; ++ch) {
        cp_wait1();
        __syncthreads();                 // all warps past chunk ch-1's buffer
        const float* src = (ch + 2 < NCHK) ? (W + (ch + 2) * CHF)
                                           : (Wnext + (ch + 2 - NCHK) * CHF);
        int stslot = slot + 2; if (stslot >= 3) stslot -= 3;
        stage_chunk(ws + stslot * CHF, src, t);
        cp_commit();
        chunk_fma(in, ws + slot * CHF, acc, r0, c0, ch * KCH);
        slot = (slot == 2) ? 0 : slot + 1;
    }
}

__device__ __forceinline__ void acc_zero(F2 (&acc)[8][2]) {
#pragma unroll
    for (int r = 0; r < 8; ++r) { acc[r][0] = f2mk(0.f, 0.f); acc[r][1] = f2mk(0.f, 0.f); }
}
__device__ __forceinline__ void acc_bias(F2 (&acc)[8][2], const float* __restrict__ bias,
                                         int c0, float s) {
    float4 b = *reinterpret_cast<const float4*>(bias + c0);
#pragma unroll
    for (int r = 0; r < 8; ++r) {
        acc[r][0] = f2mk(b.x * s, b.y * s);
        acc[r][1] = f2mk(b.z * s, b.w * s);
    }
}
__device__ __forceinline__ void acc_from_smem(F2 (&acc)[8][2], const float* __restrict__ src,
                                              int r0, int c0) {
#pragma unroll
    for (int r = 0; r < 8; ++r) {
        float4 v = *reinterpret_cast<const float4*>(src + (r0 + r) * H + c0);
        acc[r][0] = f2mk(v.x, v.y);
        acc[r][1] = f2mk(v.z, v.w);
    }
}
__device__ __forceinline__ void acc_store(float* __restrict__ out, F2 (&acc)[8][2],
                                          int r0, int c0, bool relu) {
#pragma unroll
    for (int r = 0; r < 8; ++r) {
        float4 v = make_float4(acc[r][0].f.x, acc[r][0].f.y, acc[r][1].f.x, acc[r][1].f.y);
        if (relu) {
            v.x = fmaxf(v.x, 0.f); v.y = fmaxf(v.y, 0.f);
            v.z = fmaxf(v.z, 0.f); v.w = fmaxf(v.w, 0.f);
        }
        *reinterpret_cast<float4*>(out + (r0 + r) * H + c0) = v;
    }
}

__global__ void __launch_bounds__(THREADS, 4)
rrn_kernel(const int* __restrict__ sources, const int* __restrict__ targets,
           const int* __restrict__ types, const int* __restrict__ diffs,
           const int* __restrict__ question,
           const float* __restrict__ pre_w1, const float* __restrict__ pre_b1,
           const float* __restrict__ pre_w2, const float* __restrict__ pre_b2,
           const float* __restrict__ msg_w1, const float* __restrict__ msg_b1,
           const float* __restrict__ msg_w2, const float* __restrict__ msg_b2,
           const float* __restrict__ node_w1, const float* __restrict__ node_b1,
           const float* __restrict__ node_w2, const float* __restrict__ node_b2,
           const float* __restrict__ out_w1, const float* __restrict__ out_b1,
           const float* __restrict__ out_w2, const float* __restrict__ out_b2,
           float* __restrict__ out)
{
    extern __shared__ float sm[];
    float* sh_h = sm;                     // current hidden state (16KB)
    float* sh_S = sm + 4096;              // scratch: feats / A / S / m_agg / hidden / pooled
    float* ws   = sm + 8192;              // cp.async W ring: 3 x 8KB

    const int t    = threadIdx.x;
    const int cta  = blockIdx.x;
    const int warp = t >> 5;              // == graph within CTA
    const int r0   = warp * 8;
    const int c0   = (t & 31) * 4;
    const int node0 = cta * MROWS;

    const float* msg_w1b  = msg_w1 + 128 * H;
    const float* node_w1b = node_w1 + 128 * H;
    const float* node_w1c = node_w1 + 256 * H;

    // ---- pre-MLP hidden = relu(one-hot gather of pre_w1 rows + b1) -> sh_S
    {
        const float b1 = pre_b1[t];
        for (int m = 0; m < MROWS; ++m) {
            const int node = node0 + m;
            const int b  = node >> 3;
            const int s  = sources[node];
            const int tg = targets[node];
            const int ty = types[node];
            const int d  = diffs[node];
            const int q  = question[b];
            float v = pre_w1[s * H + t] + pre_w1[(8 + tg) * H + t]
                    + pre_w1[(16 + ty) * H + t] + pre_w1[(19 + d) * H + t]
                    + pre_w1[(119 + q) * H + t] + b1;
            sh_S[m * H + t] = fmaxf(v, 0.f);
        }
    }
    __syncthreads();

    // ---- start the continuous weight chain: prime with pre_w2 chunks 0,1
    int slot = 0;
    stage_chunk(ws, pre_w2, t);           cp_commit();
    stage_chunk(ws + CHF, pre_w2 + CHF, t); cp_commit();

    // ---- x = hidden @ pre_w2 + pre_b2 -> sh_h  (h0 = x)
    {
        F2 acc[8][2];
        acc_bias(acc, pre_b2, c0, 1.0f);
        gemm_chain(sh_S, pre_w2, node_w1, acc, r0, c0, t, ws, slot);
        acc_store(sh_h, acc, r0, c0, false);
        __syncwarp();
    }

    // ---- xw = x @ node_w1[0:128] + node_b1 -> g_xw (step-invariant, global)
    {
        F2 acc[8][2];
        acc_bias(acc, node_b1, c0, 1.0f);
        gemm_chain(sh_h, node_w1, msg_w1, acc, r0, c0, t, ws, slot);
        acc_store(g_xw + node0 * H, acc, r0, c0, false);
    }

    const float4 b1v = *reinterpret_cast<const float4*>(msg_b1 + c0);
    const float bias1[4] = {b1v.x, b1v.y, b1v.z, b1v.w};

    for (int step = 0; step < NSTEPS; ++step) {
        // A = h @ msg_w1[0:128]  -> park in sh_S (own slots)
        {
            F2 acc[8][2];
            acc_zero(acc);
            gemm_chain(sh_h, msg_w1, msg_w1b, acc, r0, c0, t, ws, slot);
            acc_store(sh_S, acc, r0, c0, false);
        }
        // B = h @ msg_w1[128:256]  (registers)
        F2 accB[8][2];
        acc_zero(accB);
        gemm_chain(sh_h, msg_w1b, msg_w2, accB, r0, c0, t, ws, slot);

        // S_i = sum_{j != i} relu(A_i + B_j + b1): thread-local (8 rows x 4 cols)
        {
            F2 accA[8][2];
            acc_from_smem(accA, sh_S, r0, c0);   // reload A (same thread wrote it)
#pragma unroll
            for (int cc = 0; cc < 4; ++cc) {
                const int p = cc >> 1, hl = cc & 1;
                float A[8], Bv[8];
#pragma unroll
                for (int r = 0; r < 8; ++r) {
                    A[r]  = hl ? accA[r][p].f.y : accA[r][p].f.x;
                    Bv[r] = hl ? accB[r][p].f.y : accB[r][p].f.x;
                }
                const float bc = bias1[cc];
#pragma unroll
                for (int i = 0; i < 8; ++i) {
                    float s = 0.f;
#pragma unroll
                    for (int j = 0; j < 8; ++j) s += fmaxf(A[i] + Bv[j] + bc, 0.f);
                    s -= fmaxf(A[i] + Bv[i] + bc, 0.f);    // drop self-edge
                    if (hl) accA[i][p].f.y = s; else accA[i][p].f.x = s;
                }
            }
            acc_store(sh_S, accA, r0, c0, false);          // S -> own slots
            __syncwarp();
        }

        // m_agg = S @ msg_w2 + 7*msg_b2 -> sh_S (own slots)
        {
            F2 acc[8][2];
            acc_bias(acc, msg_b2, c0, 7.0f);
            gemm_chain(sh_S, msg_w2, node_w1b, acc, r0, c0, t, ws, slot);
            acc_store(sh_S, acc, r0, c0, false);
            __syncwarp();
        }

        // hidden = relu(xw + h@Wn1b + m_agg@Wn1c) -> sh_S (own slots)
        {
            F2 acc[8][2];
#pragma unroll
            for (int r = 0; r < 8; ++r) {    // acc := xw (own tile, coalesced LDG)
                float4 v = *reinterpret_cast<const float4*>(
                    g_xw + (node0 + r0 + r) * H + c0);
                acc[r][0] = f2mk(v.x, v.y);
                acc[r][1] = f2mk(v.z, v.w);
            }
            gemm_chain(sh_h, node_w1b, node_w1c, acc, r0, c0, t, ws, slot);
            gemm_chain(sh_S, node_w1c, node_w2, acc, r0, c0, t, ws, slot);
            acc_store(sh_S, acc, r0, c0, true);
            __syncwarp();
        }

        // h_new = hidden @ node_w2 + node_b2 -> sh_h ; pooled from regs
        {
            F2 acc[8][2];
            acc_bias(acc, node_b2, c0, 1.0f);
            const float* nextW = (step + 1 < NSTEPS) ? msg_w1 : pre_w2;  // dummy at end
            gemm_chain(sh_S, node_w2, nextW, acc, r0, c0, t, ws, slot);
            acc_store(sh_h, acc, r0, c0, false);
            float4 pool = make_float4(0.f, 0.f, 0.f, 0.f);
#pragma unroll
            for (int r = 0; r < 8; ++r) {
                pool.x += acc[r][0].f.x; pool.y += acc[r][0].f.y;
                pool.z += acc[r][1].f.x; pool.w += acc[r][1].f.y;
            }
            __syncthreads();               // all warps done reading sh_S rows
            *reinterpret_cast<float4*>(sh_S + warp * H + c0) = pool;  // row g = graph g
        }
        __syncthreads();

        // out hidden = relu(pooled @ out_w1 + out_b1) -> sh_S rows 4..7
        {
            float acc[NG];
            const float ob = out_b1[t];
#pragma unroll
            for (int g = 0; g < NG; ++g) acc[g] = ob;
#pragma unroll 8
            for (int k = 0; k < H; ++k) {
                const float w = out_w1[k * H + t];
#pragma unroll
                for (int g = 0; g < NG; ++g) acc[g] += sh_S[g * H + k] * w;
            }
#pragma unroll
            for (int g = 0; g < NG; ++g) sh_S[(4 + g) * H + t] = fmaxf(acc[g], 0.f);
        }
        __syncthreads();

        // logits = oh @ out_w2 + out_b2 -> gmem [step][bs][100]
        if (t < 100) {
            float acc[NG];
            const float ob = out_b2[t];
#pragma unroll
            for (int g = 0; g < NG; ++g) acc[g] = ob;
#pragma unroll 8
            for (int k = 0; k < H; ++k) {
                const float w = out_w2[k * 100 + t];
#pragma unroll
                for (int g = 0; g < NG; ++g) acc[g] += sh_S[(4 + g) * H + k] * w;
            }
#pragma unroll
            for (int g = 0; g < NG; ++g)
                out[(step * BS + cta * NG + g) * 100 + t] = acc[g];
        }
        // next iteration's first gemm_chain begins with wait1+syncthreads
    }

    cp_wait0();                            // drain outstanding prefetches before exit
}

extern "C" void kernel_launch(void* const* d_in, const int* in_sizes, int n_in,
                              void* d_out, int out_size) {
    (void)in_sizes; (void)n_in; (void)out_size;
    const int*   sources  = (const int*)  d_in[0];
    const int*   targets  = (const int*)  d_in[1];
    const int*   types    = (const int*)  d_in[2];
    const int*   diffs    = (const int*)  d_in[3];
    const int*   question = (const int*)  d_in[4];
    const float* pre_w1   = (const float*)d_in[5];
    const float* pre_b1   = (const float*)d_in[6];
    const float* pre_w2   = (const float*)d_in[7];
    const float* pre_b2   = (const float*)d_in[8];
    const float* msg_w1   = (const float*)d_in[9];
    const float* msg_b1   = (const float*)d_in[10];
    const float* msg_w2   = (const float*)d_in[11];
    const float* msg_b2   = (const float*)d_in[12];
    const float* node_w1  = (const float*)d_in[13];
    const float* node_b1  = (const float*)d_in[14];
    const float* node_w2  = (const float*)d_in[15];
    const float* node_b2  = (const float*)d_in[16];
    const float* out_w1   = (const float*)d_in[17];
    const float* out_b1   = (const float*)d_in[18];
    const float* out_w2   = (const float*)d_in[19];
    const float* out_b2   = (const float*)d_in[20];

    const size_t smem = (2 * 4096 + 3 * CHF) * sizeof(float);  // 32KB + 24KB = 56KB
    cudaFuncSetAttribute(rrn_kernel, cudaFuncAttributeMaxDynamicSharedMemorySize,
                         (int)smem);

    rrn_kernel<<<BS / NG, THREADS, smem>>>(
        sources, targets, types, diffs, question,
        pre_w1, pre_b1, pre_w2, pre_b2,
        msg_w1, msg_b1, msg_w2, msg_b2,
        node_w1, node_b1, node_w2, node_b2,
        out_w1, out_b1, out_w2, out_b2,
        (float*)d_out);
}